// round 16
// baseline (speedup 1.0000x reference)
#include <cuda_runtime.h>
#include <cuda_fp16.h>
#include <cstdint>

// ======================= problem constants =======================
#define DIMX     64
#define HIDX     256
#define NSTEPS   32
#define NTHREADS 384          // 12 warps = 6 pairs, 3 warps/SMSP

// grid: 1332 big CTAs (96 rows = 6 pairs) = 9 waves, then 100 tail CTAs
// (32 rows = 2 pairs). 1332*96 + 100*32 = 131072.
#define NBIG     1332
#define NTAIL    100
#define BIGROWS  (NBIG * 96)

// ======================= SMEM layout (bytes) =====================
#define SM_B1P  0
#define SM_TW1P 512
#define SM_B2P  1024
#define SM_DB3  3072
#define SM_W1   4096          // 256n x 64k f16 SW128                  (32768 B)
#define SM_W2   36864         // 4 k-chunks x (256n x 64k)             (131072 B)
#define SM_W3   167936        // 4 k-chunks x (64n x 64k), x dt        (32768 B)
#define SM_XCHG 200704        // 6 pairs x 4096 B exchange blocks      (24576 B)
#define SMEM_BYTES (200704 + 6 * 4096)

#define SWZ(off) ((off) ^ (((off) >> 3) & 0x70))

// ======================= device helpers ==========================
__device__ __forceinline__ uint32_t smem_to_u32(const void* p) {
    uint32_t a;
    asm("{ .reg .u64 t; cvta.to.shared.u64 t, %1; cvt.u32.u64 %0, t; }" : "=r"(a) : "l"(p));
    return a;
}
__device__ __forceinline__ uint32_t pack_f16x2(float lo, float hi) {
    uint32_t r;
    asm("cvt.rn.f16x2.f32 %0, %1, %2;" : "=r"(r) : "f"(hi), "f"(lo));
    return r;
}
__device__ __forceinline__ uint32_t silu2h(uint32_t ah, uint32_t h05) {
    uint32_t t, s, h;
    asm("mul.rn.f16x2 %0, %1, %2;"     : "=r"(t) : "r"(ah), "r"(h05));
    asm("tanh.approx.f16x2 %0, %1;"    : "=r"(t) : "r"(t));
    asm("fma.rn.f16x2 %0, %1, %2, %2;" : "=r"(s) : "r"(t), "r"(h05));
    asm("mul.rn.f16x2 %0, %1, %2;"     : "=r"(h) : "r"(ah), "r"(s));
    return h;
}
__device__ __forceinline__ uint32_t hfma2(uint32_t a, uint32_t b, uint32_t c) {
    uint32_t r;
    asm("fma.rn.f16x2 %0, %1, %2, %3;" : "=r"(r) : "r"(a), "r"(b), "r"(c));
    return r;
}
__device__ __forceinline__ uint32_t hadd2(uint32_t a, uint32_t b) {
    uint32_t r;
    asm("add.rn.f16x2 %0, %1, %2;" : "=r"(r) : "r"(a), "r"(b));
    return r;
}
__device__ __forceinline__ void ldsm4(uint32_t& r0, uint32_t& r1, uint32_t& r2, uint32_t& r3,
                                      uint32_t addr) {
    asm volatile("ldmatrix.sync.aligned.m8n8.x4.shared.b16 {%0,%1,%2,%3}, [%4];"
                 : "=r"(r0), "=r"(r1), "=r"(r2), "=r"(r3) : "r"(addr));
}
__device__ __forceinline__ void mma_h(uint32_t* d, const uint32_t* a, uint32_t b0, uint32_t b1) {
    asm volatile("mma.sync.aligned.m16n8k16.row.col.f16.f16.f16.f16 "
                 "{%0,%1}, {%2,%3,%4,%5}, {%6,%7}, {%0,%1};"
                 : "+r"(d[0]), "+r"(d[1])
                 : "r"(a[0]), "r"(a[1]), "r"(a[2]), "r"(a[3]), "r"(b0), "r"(b1));
}
__device__ __forceinline__ void mma_f(float* c, const uint32_t* a, uint32_t b0, uint32_t b1) {
    asm volatile("mma.sync.aligned.m16n8k16.row.col.f32.f16.f16.f32 "
                 "{%0,%1,%2,%3}, {%4,%5,%6,%7}, {%8,%9}, {%0,%1,%2,%3};"
                 : "+f"(c[0]), "+f"(c[1]), "+f"(c[2]), "+f"(c[3])
                 : "r"(a[0]), "r"(a[1]), "r"(a[2]), "r"(a[3]), "r"(b0), "r"(b1));
}
#define PBAR(id) asm volatile("bar.sync %0, 64;" :: "r"(id) : "memory")

// ======================= per-warp body (pair K-split) =============
__device__ __forceinline__ void flow_body(
    long pairRowBase, int half, int barId,
    const float* __restrict__ x0, float* __restrict__ out,
    uint32_t sbase, char* xchg,
    const uint32_t* sb1p, const uint32_t* stw1p,
    const uint32_t* sb2p, const float* sdb3, int lane)
{
    const int r = lane & 7, g = lane >> 3;
    const uint32_t ld_row = (uint32_t)((r + ((g >> 1) << 3)) * 128);
    const uint32_t g1 = (uint32_t)(g & 1);
    #define KOFF(kt) ((((uint32_t)(((kt) << 1) | g1) ^ (uint32_t)r) << 4))

    const float dt = 1.0f / NSTEPS;
    const uint32_t h05 = 0x38003800u;
    const long rowA = pairRowBase + (lane >> 2);
    const long rowB = rowA + 8;
    const int  q2 = (lane & 3) * 2;
    const int  l4 = lane & 3;

    // per-half folded bases
    const uint32_t w1half = sbase + SM_W1 + (uint32_t)half * 16384 + ld_row;  // pairs half*8..+7
    const uint32_t w2half = sbase + SM_W2 + (uint32_t)half * 65536 + ld_row;  // k-tiles half*8..+7
    const uint32_t w3hoff = (uint32_t)half * 4096;                            // n-tiles half*2..+1
    const uint32_t* sb1h  = sb1p  + half * 64;
    const uint32_t* stw1h = stw1p + half * 64;
    char* myC2 = xchg + half * 1024;          // within slot
    char* peC2 = xchg + (half ^ 1) * 1024;
    char* myV  = xchg + half * 2048;          // v region (slot-overlapping, bar-protected)
    char* peV  = xchg + (half ^ 1) * 2048;

    // ---- load x (both warps of a pair load the SAME 16 rows) ----
    float x[32];
    #pragma unroll
    for (int nt = 0; nt < 8; nt++) {
        float2 a = *(const float2*)(x0 + rowA * DIMX + nt * 8 + q2);
        float2 b = *(const float2*)(x0 + rowB * DIMX + nt * 8 + q2);
        x[nt * 4 + 0] = a.x; x[nt * 4 + 1] = a.y;
        x[nt * 4 + 2] = b.x; x[nt * 4 + 3] = b.y;
    }

    uint32_t hA[32];   // h1 for own 128-col half = own GEMM2 k-half

    #pragma unroll 1
    for (int s = 0; s < NSTEPS; s++) {
        const float tvalf = ((float)s + 0.5f) * dt;
        const uint32_t tval2 = pack_f16x2(tvalf, tvalf);

        // ======== GEMM1 (own n-half: 8 pairs, f16 accum) ========
        #pragma unroll
        for (int p = 0; p < 8; p++) {
            const uint32_t biasA = hfma2(tval2, stw1h[p * 8 + l4],     sb1h[p * 8 + l4]);
            const uint32_t biasB = hfma2(tval2, stw1h[p * 8 + 4 + l4], sb1h[p * 8 + 4 + l4]);
            uint32_t* h = hA + p * 4;
            h[0] = biasA; h[1] = biasA; h[2] = biasB; h[3] = biasB;
        }
        #pragma unroll
        for (int kt = 0; kt < 4; kt++) {
            uint32_t xk[4];
            {
                const float* xs = x + 2 * kt * 4;
                xk[0] = pack_f16x2(xs[0], xs[1]);
                xk[1] = pack_f16x2(xs[2], xs[3]);
                xk[2] = pack_f16x2(xs[4], xs[5]);
                xk[3] = pack_f16x2(xs[6], xs[7]);
            }
            const uint32_t koff = KOFF(kt);
            #pragma unroll
            for (int p = 0; p < 8; p++) {
                uint32_t w0, w1_, w2_, w3_;
                ldsm4(w0, w1_, w2_, w3_, w1half + (uint32_t)(p * 2048) + koff);
                mma_h(hA + p * 4 + 0, xk, w0,  w1_);
                mma_h(hA + p * 4 + 2, xk, w2_, w3_);
            }
        }
        #pragma unroll
        for (int i = 0; i < 32; i++) hA[i] = silu2h(hA[i], h05);

        // ======== GEMM2 k-half + pair exchange + GEMM3 n-half ========
        float v[16];
        #pragma unroll
        for (int i = 0; i < 16; i++) v[i] = 0.0f;

        #pragma unroll
        for (int ch = 0; ch < 8; ch++) {
            uint32_t C2[8];
            if (half == 0) {
                #pragma unroll
                for (int nt = 0; nt < 4; nt++) {
                    const uint32_t b2v = sb2p[ch * 16 + nt * 4 + l4];
                    C2[nt * 2 + 0] = b2v; C2[nt * 2 + 1] = b2v;
                }
            } else {
                #pragma unroll
                for (int i = 0; i < 8; i++) C2[i] = 0u;
            }

            // ---- 8 k-tiles of own half, B-fragments double-buffered ----
            const uint32_t w2base = w2half + (uint32_t)(ch * 4096);
            uint32_t B0[4], B1[4];
            ldsm4(B0[0], B0[1], B0[2], B0[3], w2base + KOFF(0));
            ldsm4(B1[0], B1[1], B1[2], B1[3], w2base + 2048u + KOFF(0));
            #pragma unroll
            for (int ktl = 0; ktl < 8; ktl++) {
                uint32_t N0[4], N1[4];
                if (ktl < 7) {
                    const int kn = ktl + 1;
                    const uint32_t ko = (uint32_t)((kn >> 2) * 32768) + KOFF(kn & 3);
                    ldsm4(N0[0], N0[1], N0[2], N0[3], w2base + ko);
                    ldsm4(N1[0], N1[1], N1[2], N1[3], w2base + 2048u + ko);
                }
                const uint32_t* a = hA + ktl * 4;
                mma_h(C2 + 0, a, B0[0], B0[1]);
                mma_h(C2 + 2, a, B0[2], B0[3]);
                mma_h(C2 + 4, a, B1[0], B1[1]);
                mma_h(C2 + 6, a, B1[2], B1[3]);
                if (ktl < 7) {
                    #pragma unroll
                    for (int j = 0; j < 4; j++) { B0[j] = N0[j]; B1[j] = N1[j]; }
                }
            }

            // ---- exchange partial C2 with pair partner ----
            {
                char* slot = xchg + (ch & 1) * 2048;
                *(uint4*)(slot + (half * 1024) + lane * 32) =
                    make_uint4(C2[0], C2[1], C2[2], C2[3]);
                *(uint4*)(slot + (half * 1024) + lane * 32 + 16) =
                    make_uint4(C2[4], C2[5], C2[6], C2[7]);
                PBAR(barId);
                uint4 a0 = *(const uint4*)(slot + ((half ^ 1) * 1024) + lane * 32);
                uint4 a1 = *(const uint4*)(slot + ((half ^ 1) * 1024) + lane * 32 + 16);
                C2[0] = hadd2(C2[0], a0.x); C2[1] = hadd2(C2[1], a0.y);
                C2[2] = hadd2(C2[2], a0.z); C2[3] = hadd2(C2[3], a0.w);
                C2[4] = hadd2(C2[4], a1.x); C2[5] = hadd2(C2[5], a1.y);
                C2[6] = hadd2(C2[6], a1.z); C2[7] = hadd2(C2[7], a1.w);
            }
            #pragma unroll
            for (int i = 0; i < 8; i++) C2[i] = silu2h(C2[i], h05);

            // ---- GEMM3 n-half: v += silu(C2) @ (dt*W3)[k-slices 2ch,2ch+1] ----
            #pragma unroll
            for (int p2 = 0; p2 < 2; p2++) {
                uint32_t af[4];
                af[0] = C2[(2 * p2) * 2 + 0];
                af[1] = C2[(2 * p2) * 2 + 1];
                af[2] = C2[(2 * p2 + 1) * 2 + 0];
                af[3] = C2[(2 * p2 + 1) * 2 + 1];
                const int kt3 = ch * 2 + p2;
                const uint32_t w3base = sbase + SM_W3 + (uint32_t)((kt3 >> 2) * 8192)
                                        + ld_row + w3hoff;
                const uint32_t k3off = KOFF(kt3 & 3);
                #pragma unroll
                for (int ntl = 0; ntl < 2; ntl++) {
                    uint32_t w0, w1_, w2_, w3_;
                    ldsm4(w0, w1_, w2_, w3_, w3base + (uint32_t)(ntl * 2048) + k3off);
                    mma_f(v + (2 * ntl) * 4,     af, w0,  w1_);
                    mma_f(v + (2 * ntl + 1) * 4, af, w2_, w3_);
                }
            }
        }

        // ---- v exchange (barrier-protected; v region overlaps chunk slots) ----
        PBAR(barId);
        *(float4*)(myV +  0 + lane * 64) = make_float4(v[0],  v[1],  v[2],  v[3]);
        *(float4*)(myV + 16 + lane * 64) = make_float4(v[4],  v[5],  v[6],  v[7]);
        *(float4*)(myV + 32 + lane * 64) = make_float4(v[8],  v[9],  v[10], v[11]);
        *(float4*)(myV + 48 + lane * 64) = make_float4(v[12], v[13], v[14], v[15]);
        PBAR(barId);
        float vp[16];
        {
            float4 a0 = *(const float4*)(peV +  0 + lane * 64);
            float4 a1 = *(const float4*)(peV + 16 + lane * 64);
            float4 a2 = *(const float4*)(peV + 32 + lane * 64);
            float4 a3 = *(const float4*)(peV + 48 + lane * 64);
            vp[0]=a0.x; vp[1]=a0.y; vp[2]=a0.z; vp[3]=a0.w;
            vp[4]=a1.x; vp[5]=a1.y; vp[6]=a1.z; vp[7]=a1.w;
            vp[8]=a2.x; vp[9]=a2.y; vp[10]=a2.z; vp[11]=a2.w;
            vp[12]=a3.x; vp[13]=a3.y; vp[14]=a3.z; vp[15]=a3.w;
        }
        PBAR(barId);   // protect v region before next step's chunk writes

        // ---- x += dt*b3 + v(even cols) + v(odd cols) — identical order both warps ----
        #pragma unroll
        for (int nt = 0; nt < 8; nt++) {
            float2 p = *(const float2*)(sdb3 + nt * 8 + q2);
            float* xs = x + nt * 4;
            xs[0] += p.x; xs[1] += p.y; xs[2] += p.x; xs[3] += p.y;
        }
        if (half == 0) {
            #pragma unroll
            for (int i = 0; i < 16; i++) { x[i] += v[i]; x[16 + i] += vp[i]; }
        } else {
            #pragma unroll
            for (int i = 0; i < 16; i++) { x[i] += vp[i]; x[16 + i] += v[i]; }
        }
    }

    // ---- store result (even warp only — both hold identical x) ----
    if (half == 0) {
        #pragma unroll
        for (int nt = 0; nt < 8; nt++) {
            const float* xs = x + nt * 4;
            *(float2*)(out + rowA * DIMX + nt * 8 + q2) = make_float2(xs[0], xs[1]);
            *(float2*)(out + rowB * DIMX + nt * 8 + q2) = make_float2(xs[2], xs[3]);
        }
    }
    #undef KOFF
}

// ======================= kernel ==================================
__global__ void __launch_bounds__(NTHREADS, 1) flow_kernel(
    const float* __restrict__ x0, const float* __restrict__ W1,
    const float* __restrict__ b1, const float* __restrict__ W2,
    const float* __restrict__ b2, const float* __restrict__ W3,
    const float* __restrict__ b3, float* __restrict__ out)
{
    extern __shared__ char smem[];
    const uint32_t sbase = smem_to_u32(smem);
    const int tid = threadIdx.x;
    const int wid = tid >> 5;
    const int lane = tid & 31;

    uint32_t* sb1p  = (uint32_t*)(smem + SM_B1P);
    uint32_t* stw1p = (uint32_t*)(smem + SM_TW1P);
    uint32_t* sb2p  = (uint32_t*)(smem + SM_B2P);
    float*    sdb3  = (float*)(smem + SM_DB3);

    const float dt = 1.0f / NSTEPS;

    if (tid < 128) {
        sb1p[tid]  = pack_f16x2(b1[2 * tid], b1[2 * tid + 1]);
        stw1p[tid] = pack_f16x2(W1[DIMX * HIDX + 2 * tid], W1[DIMX * HIDX + 2 * tid + 1]);
        sb2p[tid]  = pack_f16x2(b2[2 * tid], b2[2 * tid + 1]);
    }
    if (tid < DIMX) sdb3[tid] = dt * b3[tid];

    for (int idx = tid; idx < DIMX * HIDX; idx += NTHREADS) {          // W1 (64k,256n)
        int k = idx >> 8, n = idx & 255;
        uint32_t off = (uint32_t)(n * 128 + k * 2);
        *(__half*)(smem + SM_W1 + SWZ(off)) = __float2half(W1[idx]);
    }
    for (int idx = tid; idx < HIDX * HIDX; idx += NTHREADS) {          // W2 (256k,256n)
        int k = idx >> 8, n = idx & 255;
        int c = k >> 6, kk = k & 63;
        uint32_t off = (uint32_t)(n * 128 + kk * 2);
        *(__half*)(smem + SM_W2 + c * 32768 + SWZ(off)) = __float2half(W2[idx]);
    }
    for (int idx = tid; idx < HIDX * DIMX; idx += NTHREADS) {          // W3 (256k,64n), x dt
        int k = idx >> 6, n = idx & 63;
        int c = k >> 6, kk = k & 63;
        uint32_t off = (uint32_t)(n * 128 + kk * 2);
        *(__half*)(smem + SM_W3 + c * 8192 + SWZ(off)) = __float2half(dt * W3[idx]);
    }
    __syncthreads();

    const int half   = wid & 1;
    const int pairId = wid >> 1;
    char* xchg = smem + SM_XCHG + pairId * 4096;

    if (blockIdx.x < NBIG) {
        flow_body((long)blockIdx.x * 96 + pairId * 16, half, pairId + 1,
                  x0, out, sbase, xchg, sb1p, stw1p, sb2p, sdb3, lane);
    } else {
        if (wid >= 4) return;   // tail CTA: 2 pairs (32 rows)
        flow_body((long)BIGROWS + (long)(blockIdx.x - NBIG) * 32 + pairId * 16,
                  half, pairId + 1,
                  x0, out, sbase, xchg, sb1p, stw1p, sb2p, sdb3, lane);
    }
}

// ======================= launch ==================================
extern "C" void kernel_launch(void* const* d_in, const int* in_sizes, int n_in,
                              void* d_out, int out_size) {
    const float* x0 = (const float*)d_in[0];
    const float* W1 = (const float*)d_in[1];
    const float* b1 = (const float*)d_in[2];
    const float* W2 = (const float*)d_in[3];
    const float* b2 = (const float*)d_in[4];
    const float* W3 = (const float*)d_in[5];
    const float* b3 = (const float*)d_in[6];
    float* out = (float*)d_out;

    cudaFuncSetAttribute(flow_kernel, cudaFuncAttributeMaxDynamicSharedMemorySize, SMEM_BYTES);
    flow_kernel<<<NBIG + NTAIL, NTHREADS, SMEM_BYTES>>>(x0, W1, b1, W2, b2, W3, b3, out);
}

// round 17
// speedup vs baseline: 1.3919x; 1.3919x over previous
#include <cuda_runtime.h>
#include <cuda_fp16.h>
#include <cstdint>

// ======================= problem constants =======================
#define DIMX     64
#define HIDX     256
#define NSTEPS   32
#define NTHREADS 384          // 12 warps -> 3 warps per SMSP

// uniform grid: 682 CTAs x 192 rows (12 warps x m16) + 1 CTA x 128 rows
// (8 active warps). 682*192 + 128 = 131072. Tail wave (91 CTAs) runs at
// full 3-warp/SMSP occupancy, unlike a degraded 8-warp tail.
#define NBIG     682
#define BIGROWS  (NBIG * 192)

// ======================= SMEM layout (bytes) =====================
#define SM_B1P  0
#define SM_TW1P 512
#define SM_B2P  1024
#define SM_DB3  3072
#define SM_W1   4096
#define SM_W2   36864
#define SM_W3   167936
#define SMEM_BYTES 200704

#define SWZ(off) ((off) ^ (((off) >> 3) & 0x70))

// ======================= device helpers ==========================
__device__ __forceinline__ uint32_t smem_to_u32(const void* p) {
    uint32_t a;
    asm("{ .reg .u64 t; cvta.to.shared.u64 t, %1; cvt.u32.u64 %0, t; }" : "=r"(a) : "l"(p));
    return a;
}
__device__ __forceinline__ uint32_t pack_f16x2(float lo, float hi) {
    uint32_t r;
    asm("cvt.rn.f16x2.f32 %0, %1, %2;" : "=r"(r) : "f"(hi), "f"(lo));
    return r;
}
__device__ __forceinline__ uint32_t silu2h(uint32_t ah, uint32_t h05) {
    uint32_t t, s, h;
    asm("mul.rn.f16x2 %0, %1, %2;"     : "=r"(t) : "r"(ah), "r"(h05));
    asm("tanh.approx.f16x2 %0, %1;"    : "=r"(t) : "r"(t));
    asm("fma.rn.f16x2 %0, %1, %2, %2;" : "=r"(s) : "r"(t), "r"(h05));
    asm("mul.rn.f16x2 %0, %1, %2;"     : "=r"(h) : "r"(ah), "r"(s));
    return h;
}
__device__ __forceinline__ uint32_t hfma2(uint32_t a, uint32_t b, uint32_t c) {
    uint32_t r;
    asm("fma.rn.f16x2 %0, %1, %2, %3;" : "=r"(r) : "r"(a), "r"(b), "r"(c));
    return r;
}
__device__ __forceinline__ void ldsm4(uint32_t& r0, uint32_t& r1, uint32_t& r2, uint32_t& r3,
                                      uint32_t addr) {
    asm volatile("ldmatrix.sync.aligned.m8n8.x4.shared.b16 {%0,%1,%2,%3}, [%4];"
                 : "=r"(r0), "=r"(r1), "=r"(r2), "=r"(r3) : "r"(addr));
}
__device__ __forceinline__ void mma_h(uint32_t* d, const uint32_t* a, uint32_t b0, uint32_t b1) {
    asm volatile("mma.sync.aligned.m16n8k16.row.col.f16.f16.f16.f16 "
                 "{%0,%1}, {%2,%3,%4,%5}, {%6,%7}, {%0,%1};"
                 : "+r"(d[0]), "+r"(d[1])
                 : "r"(a[0]), "r"(a[1]), "r"(a[2]), "r"(a[3]), "r"(b0), "r"(b1));
}
__device__ __forceinline__ void mma_f(float* c, const uint32_t* a, uint32_t b0, uint32_t b1) {
    asm volatile("mma.sync.aligned.m16n8k16.row.col.f32.f16.f16.f32 "
                 "{%0,%1,%2,%3}, {%4,%5,%6,%7}, {%8,%9}, {%0,%1,%2,%3};"
                 : "+f"(c[0]), "+f"(c[1]), "+f"(c[2]), "+f"(c[3])
                 : "r"(a[0]), "r"(a[1]), "r"(a[2]), "r"(a[3]), "r"(b0), "r"(b1));
}

// ======================= per-warp body (m16) ======================
__device__ __forceinline__ void flow_body(
    long rowBaseWarp, const float* __restrict__ x0, float* __restrict__ out,
    uint32_t sbase, const uint32_t* sb1p, const uint32_t* stw1p,
    const uint32_t* sb2p, const float* sdb3, int lane)
{
    const int r = lane & 7, g = lane >> 3;
    const uint32_t ld_row = (uint32_t)((r + ((g >> 1) << 3)) * 128);
    const uint32_t g1 = (uint32_t)(g & 1);
    #define KOFF(kt) ((((uint32_t)(((kt) << 1) | g1) ^ (uint32_t)r) << 4))

    const float dt = 1.0f / NSTEPS;
    const uint32_t h05 = 0x38003800u;
    const long rowA = rowBaseWarp + (lane >> 2);
    const long rowB = rowA + 8;
    const int  q2 = (lane & 3) * 2;
    const int  l4 = lane & 3;

    float x[32];
    #pragma unroll
    for (int nt = 0; nt < 8; nt++) {
        float2 a = *(const float2*)(x0 + rowA * DIMX + nt * 8 + q2);
        float2 b = *(const float2*)(x0 + rowB * DIMX + nt * 8 + q2);
        x[nt * 4 + 0] = a.x; x[nt * 4 + 1] = a.y;
        x[nt * 4 + 2] = b.x; x[nt * 4 + 3] = b.y;
    }

    uint32_t hA[64];   // GEMM1 accum -> (after fused silu) GEMM2 A frags

    #define SILU_SLICE(kt) do { \
        uint32_t* h = hA + (kt) * 4; \
        h[0] = silu2h(h[0], h05); h[1] = silu2h(h[1], h05); \
        h[2] = silu2h(h[2], h05); h[3] = silu2h(h[3], h05); } while (0)

    #define G2_INIT(ch, C2) do { \
        _Pragma("unroll") for (int nt = 0; nt < 4; nt++) { \
            const uint32_t b2v = sb2p[(ch) * 16 + nt * 4 + l4]; \
            (C2)[nt * 2 + 0] = b2v; (C2)[nt * 2 + 1] = b2v; } } while (0)

    #define G2_MMA(ch, C2, FUSE_SILU) do { \
        const uint32_t w2base = sbase + SM_W2 + (uint32_t)((ch) * 4096) + ld_row; \
        uint32_t B0[4], B1[4]; \
        ldsm4(B0[0], B0[1], B0[2], B0[3], w2base + KOFF(0)); \
        ldsm4(B1[0], B1[1], B1[2], B1[3], w2base + 2048u + KOFF(0)); \
        _Pragma("unroll") for (int kt = 0; kt < 16; kt++) { \
            uint32_t N0[4], N1[4]; \
            if (kt < 15) { \
                const int kn = kt + 1; \
                const uint32_t ko = (uint32_t)((kn >> 2) * 32768) + KOFF(kn & 3); \
                ldsm4(N0[0], N0[1], N0[2], N0[3], w2base + ko); \
                ldsm4(N1[0], N1[1], N1[2], N1[3], w2base + 2048u + ko); } \
            if ((FUSE_SILU) && kt < 15) SILU_SLICE(kt + 1); \
            const uint32_t* a = hA + kt * 4; \
            mma_h((C2) + 0, a, B0[0], B0[1]); \
            mma_h((C2) + 2, a, B0[2], B0[3]); \
            mma_h((C2) + 4, a, B1[0], B1[1]); \
            mma_h((C2) + 6, a, B1[2], B1[3]); \
            if (kt < 15) { \
                _Pragma("unroll") for (int j = 0; j < 4; j++) { B0[j] = N0[j]; B1[j] = N1[j]; } } \
        } } while (0)

    #define EPI_G3(ch, C2) do { \
        _Pragma("unroll") for (int i = 0; i < 8; i++) (C2)[i] = silu2h((C2)[i], h05); \
        _Pragma("unroll") for (int p = 0; p < 2; p++) { \
            uint32_t af[4]; \
            af[0] = (C2)[(2 * p) * 2 + 0]; \
            af[1] = (C2)[(2 * p) * 2 + 1]; \
            af[2] = (C2)[(2 * p + 1) * 2 + 0]; \
            af[3] = (C2)[(2 * p + 1) * 2 + 1]; \
            const int kt3 = (ch) * 2 + p; \
            const uint32_t w3base = sbase + SM_W3 + (uint32_t)((kt3 >> 2) * 8192) + ld_row; \
            const uint32_t k3off = KOFF(kt3 & 3); \
            _Pragma("unroll") for (int ntp = 0; ntp < 4; ntp++) { \
                uint32_t w0, w1_, w2_, w3_; \
                ldsm4(w0, w1_, w2_, w3_, w3base + (uint32_t)(ntp * 2048) + k3off); \
                mma_f(x + (2 * ntp) * 4,     af, w0,  w1_); \
                mma_f(x + (2 * ntp + 1) * 4, af, w2_, w3_); } } } while (0)

    #pragma unroll 1
    for (int s = 0; s < NSTEPS; s++) {
        const float tvalf = ((float)s + 0.5f) * dt;
        const uint32_t tval2 = pack_f16x2(tvalf, tvalf);

        // ======== GEMM1 (k-outer, f16 accum in hA) ========
        #pragma unroll
        for (int pair = 0; pair < 16; pair++) {
            const uint32_t biasA = hfma2(tval2, stw1p[pair * 8 + l4],     sb1p[pair * 8 + l4]);
            const uint32_t biasB = hfma2(tval2, stw1p[pair * 8 + 4 + l4], sb1p[pair * 8 + 4 + l4]);
            uint32_t* h = hA + pair * 4;
            h[0] = biasA; h[1] = biasA; h[2] = biasB; h[3] = biasB;
        }
        #pragma unroll
        for (int kt = 0; kt < 4; kt++) {
            uint32_t xk[4];
            {
                const float* xs = x + 2 * kt * 4;
                xk[0] = pack_f16x2(xs[0], xs[1]);
                xk[1] = pack_f16x2(xs[2], xs[3]);
                xk[2] = pack_f16x2(xs[4], xs[5]);
                xk[3] = pack_f16x2(xs[6], xs[7]);
            }
            const uint32_t koff = KOFF(kt);
            #pragma unroll
            for (int pair = 0; pair < 16; pair++) {
                uint32_t w0, w1_, w2_, w3_;
                ldsm4(w0, w1_, w2_, w3_,
                      sbase + SM_W1 + (uint32_t)(pair * 2048) + ld_row + koff);
                mma_h(hA + pair * 4 + 0, xk, w0,  w1_);
                mma_h(hA + pair * 4 + 2, xk, w2_, w3_);
            }
        }

        // ==== GEMM2+GEMM3, chunk pipeline; hA silu fused into chunk 0 ====
        {
            uint32_t C2a[8], C2b[8];
            SILU_SLICE(0);
            G2_INIT(0, C2a); G2_MMA(0, C2a, 1);
            #pragma unroll
            for (int ch = 0; ch < 8; ch += 2) {
                G2_INIT(ch + 1, C2b); G2_MMA(ch + 1, C2b, 0);
                EPI_G3(ch, C2a);
                if (ch < 6) { G2_INIT(ch + 2, C2a); G2_MMA(ch + 2, C2a, 0); }
                EPI_G3(ch + 1, C2b);
            }
        }

        // ---- x += dt * b3 ----
        #pragma unroll
        for (int nt = 0; nt < 8; nt++) {
            float2 p = *(const float2*)(sdb3 + nt * 8 + q2);
            float* xs = x + nt * 4;
            xs[0] += p.x; xs[1] += p.y; xs[2] += p.x; xs[3] += p.y;
        }
    }

    // ---- store result ----
    #pragma unroll
    for (int nt = 0; nt < 8; nt++) {
        const float* xs = x + nt * 4;
        *(float2*)(out + rowA * DIMX + nt * 8 + q2) = make_float2(xs[0], xs[1]);
        *(float2*)(out + rowB * DIMX + nt * 8 + q2) = make_float2(xs[2], xs[3]);
    }
    #undef KOFF
    #undef SILU_SLICE
    #undef G2_INIT
    #undef G2_MMA
    #undef EPI_G3
}

// ======================= kernel ==================================
__global__ void __launch_bounds__(NTHREADS, 1) flow_kernel(
    const float* __restrict__ x0, const float* __restrict__ W1,
    const float* __restrict__ b1, const float* __restrict__ W2,
    const float* __restrict__ b2, const float* __restrict__ W3,
    const float* __restrict__ b3, float* __restrict__ out)
{
    extern __shared__ char smem[];
    const uint32_t sbase = smem_to_u32(smem);
    const int tid = threadIdx.x;
    const int wid = tid >> 5;
    const int lane = tid & 31;

    uint32_t* sb1p  = (uint32_t*)(smem + SM_B1P);
    uint32_t* stw1p = (uint32_t*)(smem + SM_TW1P);
    uint32_t* sb2p  = (uint32_t*)(smem + SM_B2P);
    float*    sdb3  = (float*)(smem + SM_DB3);

    const float dt = 1.0f / NSTEPS;

    if (tid < 128) {
        sb1p[tid]  = pack_f16x2(b1[2 * tid], b1[2 * tid + 1]);
        stw1p[tid] = pack_f16x2(W1[DIMX * HIDX + 2 * tid], W1[DIMX * HIDX + 2 * tid + 1]);
        sb2p[tid]  = pack_f16x2(b2[2 * tid], b2[2 * tid + 1]);
    }
    if (tid < DIMX) sdb3[tid] = dt * b3[tid];

    for (int idx = tid; idx < DIMX * HIDX; idx += NTHREADS) {          // W1 (64k,256n)
        int k = idx >> 8, n = idx & 255;
        uint32_t off = (uint32_t)(n * 128 + k * 2);
        *(__half*)(smem + SM_W1 + SWZ(off)) = __float2half(W1[idx]);
    }
    for (int idx = tid; idx < HIDX * HIDX; idx += NTHREADS) {          // W2 (256k,256n)
        int k = idx >> 8, n = idx & 255;
        int c = k >> 6, kk = k & 63;
        uint32_t off = (uint32_t)(n * 128 + kk * 2);
        *(__half*)(smem + SM_W2 + c * 32768 + SWZ(off)) = __float2half(W2[idx]);
    }
    for (int idx = tid; idx < HIDX * DIMX; idx += NTHREADS) {          // W3 (256k,64n), x dt
        int k = idx >> 6, n = idx & 63;
        int c = k >> 6, kk = k & 63;
        uint32_t off = (uint32_t)(n * 128 + kk * 2);
        *(__half*)(smem + SM_W3 + c * 8192 + SWZ(off)) = __float2half(dt * W3[idx]);
    }
    __syncthreads();

    if (blockIdx.x < NBIG) {
        // full CTA: 12 warps x 16 rows = 192 rows
        flow_body((long)blockIdx.x * 192 + wid * 16, x0, out,
                  sbase, sb1p, stw1p, sb2p, sdb3, lane);
    } else {
        // final CTA: 128 remaining rows; warps 8-11 exit
        if (wid >= 8) return;
        flow_body((long)BIGROWS + wid * 16, x0, out,
                  sbase, sb1p, stw1p, sb2p, sdb3, lane);
    }
}

// ======================= launch ==================================
extern "C" void kernel_launch(void* const* d_in, const int* in_sizes, int n_in,
                              void* d_out, int out_size) {
    const float* x0 = (const float*)d_in[0];
    const float* W1 = (const float*)d_in[1];
    const float* b1 = (const float*)d_in[2];
    const float* W2 = (const float*)d_in[3];
    const float* b2 = (const float*)d_in[4];
    const float* W3 = (const float*)d_in[5];
    const float* b3 = (const float*)d_in[6];
    float* out = (float*)d_out;

    cudaFuncSetAttribute(flow_kernel, cudaFuncAttributeMaxDynamicSharedMemorySize, SMEM_BYTES);
    flow_kernel<<<NBIG + 1, NTHREADS, SMEM_BYTES>>>(x0, W1, b1, W2, b2, W3, b3, out);
}